// round 4
// baseline (speedup 1.0000x reference)
#include <cuda_runtime.h>
#include <cstdint>

#define T_DIM   8192
#define C_DIM   8
#define CAP     512
#define NT      512
#define NWARPS  (NT / 32)
#define SLOTS   8
#define DEPTH   4
#define NVEC    (T_DIM * C_DIM / 4)     // 16384 float4
#define GROUPS  (NVEC / (NT * DEPTH))   // 8
#define RANK0   7371                    // floor(0.9 * (T_DIM-1))
#define LO_B    0x3F9851EC              // bits of ~1.19f
#define HI_B    0x3FB0A3D7              // bits of ~1.38f
#define RANGE   (HI_B - LO_B)
#define PLANE   (4 * NT * 4)            // 8192 bytes: one [j][tid] plane stride

__device__ __constant__ float kFrac = (float)(0.9 * (double)(T_DIM - 1) - (double)RANK0);

struct SmemLayout {
    float    priv[SLOTS][4][NT];   // 64 KB private capture slots
    float    cand[C_DIM][CAP];     // 16 KB compacted candidates
    uint32_t hist[C_DIM][256];     // 8 KB radix histograms
    uint32_t cntp[NT];             // packed per-thread per-j counts
    float    wpart[NWARPS][C_DIM][3];
    int      wbelow[NWARPS][C_DIM];
    float    stat[C_DIM][4];
    int      below[C_DIM];
    int      fb[C_DIM];
    uint32_t bhist[256];
    int      bcast[2];
};

__device__ __forceinline__ uint32_t fkey(float v) {
    uint32_t u = __float_as_uint(v);
    return (u & 0x80000000u) ? ~u : (u | 0x80000000u);
}
__device__ __forceinline__ float fkey_inv(uint32_t k) {
    uint32_t u = (k & 0x80000000u) ? (k ^ 0x80000000u) : ~k;
    return __uint_as_float(u);
}

// Exact rank-r selection over n smem candidates; one warp, 4-pass byte radix.
__device__ float warp_select(const float* cand, uint32_t* hist, int n, int r) {
    const int lane = threadIdx.x & 31;
    uint32_t prefix = 0, done = 0;
    for (int shift = 24; shift >= 0; shift -= 8) {
        for (int i = lane; i < 256; i += 32) hist[i] = 0;
        __syncwarp();
        for (int i = lane; i < n; i += 32) {
            uint32_t k = fkey(cand[i]);
            if ((k & done) == prefix) atomicAdd(&hist[(k >> shift) & 255u], 1u);
        }
        __syncwarp();
        uint32_t bv[8];
        uint32_t loc = 0;
#pragma unroll
        for (int j = 0; j < 8; j++) { bv[j] = hist[lane * 8 + j]; loc += bv[j]; }
        uint32_t pre = loc;
#pragma unroll
        for (int d = 1; d < 32; d <<= 1) {
            uint32_t t = __shfl_up_sync(0xffffffffu, pre, d);
            if (lane >= d) pre += t;
        }
        int excl = (int)(pre - loc);
        bool myfind = (r >= excl) && (r < excl + (int)loc);
        uint32_t ball = __ballot_sync(0xffffffffu, myfind);
        int src = __ffs(ball) - 1;
        int bin_out = 0, rem_out = 0;
        if (myfind) {
            int rem = r - excl, bsel = 0;
            bool found = false;
#pragma unroll
            for (int j = 0; j < 8; j++) {
                if (!found) {
                    if (rem < (int)bv[j]) { bsel = j; found = true; }
                    else rem -= (int)bv[j];
                }
            }
            bin_out = lane * 8 + bsel;
            rem_out = rem;
        }
        int bin = __shfl_sync(0xffffffffu, bin_out, src);
        r       = __shfl_sync(0xffffffffu, rem_out, src);
        prefix |= (uint32_t)bin << shift;
        done   |= 0xFFu << shift;
        __syncwarp();
    }
    return fkey_inv(prefix);
}

// Block-wide exact rank-r selection from global (fallback; ~15 events per run).
__device__ float block_select_global(const float* __restrict__ x, int b, int c, int r,
                                     uint32_t* hist, int* bcast) {
    const int tid = threadIdx.x;
    uint32_t prefix = 0, done = 0;
    for (int shift = 24; shift >= 0; shift -= 8) {
        for (int i = tid; i < 256; i += NT) hist[i] = 0;
        __syncthreads();
        for (int t = tid; t < T_DIM; t += NT) {
            float v = x[((size_t)b * T_DIM + t) * C_DIM + c];
            uint32_t k = fkey(v);
            if ((k & done) == prefix) atomicAdd(&hist[(k >> shift) & 255u], 1u);
        }
        __syncthreads();
        if (tid == 0) {
            int rr = r, bin = 255;
            for (int j = 0; j < 256; j++) {
                if (rr < (int)hist[j]) { bin = j; break; }
                rr -= (int)hist[j];
            }
            bcast[0] = bin; bcast[1] = rr;
        }
        __syncthreads();
        prefix |= (uint32_t)bcast[0] << shift;
        r = bcast[1];
        done |= 0xFFu << shift;
        __syncthreads();
    }
    return fkey_inv(prefix);
}

__global__ void __launch_bounds__(NT, 2) stat_kernel(
    const float* __restrict__ x, const float* __restrict__ W,
    const float* __restrict__ bias, float* __restrict__ out)
{
    extern __shared__ unsigned char smem_raw[];
    SmemLayout* sm = reinterpret_cast<SmemLayout*>(smem_raw);

    const int tid  = threadIdx.x;
    const int lane = tid & 31;
    const int wid  = tid >> 5;
    const int b    = blockIdx.x;

    if (tid < C_DIM) sm->fb[tid] = 0;
    __syncthreads();

    const int cbase = (tid & 1) * 4;     // even tids own ch 0-3, odd own ch 4-7

    // private-slot write cursors (shared-space byte addresses) + clamps
    uint32_t addr[4], base0[4], maxa[4];
#pragma unroll
    for (int j = 0; j < 4; j++) {
        base0[j] = (uint32_t)__cvta_generic_to_shared(&sm->priv[0][j][tid]);
        addr[j]  = base0[j];
        maxa[j]  = base0[j] + (SLOTS - 1) * PLANE;
    }

    // ---- Main streaming pass: front-batched LDG.128, atomic-free capture ----
    const float4* xb = reinterpret_cast<const float4*>(x + (size_t)b * T_DIM * C_DIM);
    unsigned long long sum01 = 0, sum23 = 0, ssq01 = 0, ssq23 = 0;  // packed f32x2
    int cpos[4] = {0, 0, 0, 0};
    int cbel[4] = {0, 0, 0, 0};

#pragma unroll 1
    for (int g = 0; g < GROUPS; g++) {
        float4 buf[DEPTH];
        const int base = g * DEPTH * NT + tid;
#pragma unroll
        for (int k = 0; k < DEPTH; k++)
            buf[k] = __ldcs(&xb[base + k * NT]);

#pragma unroll
        for (int k = 0; k < DEPTH; k++) {
            float v[4] = {buf[k].x, buf[k].y, buf[k].z, buf[k].w};
            // packed sum/sumsq: 2 channels per instruction
            unsigned long long v01, v23;
            asm("mov.b64 %0, {%1, %2};" : "=l"(v01) : "f"(v[0]), "f"(v[1]));
            asm("mov.b64 %0, {%1, %2};" : "=l"(v23) : "f"(v[2]), "f"(v[3]));
            asm("add.rn.f32x2 %0, %0, %1;" : "+l"(sum01) : "l"(v01));
            asm("add.rn.f32x2 %0, %0, %1;" : "+l"(sum23) : "l"(v23));
            asm("fma.rn.f32x2 %0, %1, %1, %0;" : "+l"(ssq01) : "l"(v01));
            asm("fma.rn.f32x2 %0, %1, %1, %0;" : "+l"(ssq23) : "l"(v23));
#pragma unroll
            for (int j = 0; j < 4; j++) {
                int vb = __float_as_int(v[j]);
                cpos[j] += (vb > 0);                 // exact (int-bit order, handles -0.0)
                cbel[j] += (vb < (int)LO_B);         // exact signed compare
                uint32_t t = (uint32_t)(vb - (int)LO_B);   // in-window <=> t < RANGE (wrap-safe)
                asm volatile(
                    "{\n\t"
                    ".reg .pred pw;\n\t"
                    ".reg .b32 a;\n\t"
                    "setp.lt.u32 pw, %2, %3;\n\t"
                    "min.s32 a, %0, %4;\n\t"
                    "@pw st.shared.f32 [a], %1;\n\t"
                    "@pw add.s32 %0, %0, %5;\n\t"
                    "}\n\t"
                    : "+r"(addr[j])
                    : "f"(v[j]), "r"(t), "n"(RANGE), "r"(maxa[j]), "n"(PLANE));
            }
        }
    }

    // store packed per-thread window counts; flag overflow (lost values -> fallback)
    {
        uint32_t pk = 0;
#pragma unroll
        for (int j = 0; j < 4; j++) {
            uint32_t c = (addr[j] - base0[j]) >> 13;   // PLANE = 8192 = 2^13
            if (c > SLOTS) sm->fb[cbase + j] = 1;
            pk |= (c > 255u ? 255u : c) << (j * 8);
        }
        sm->cntp[tid] = pk;
    }

    // unpack packed accumulators
    float sum[4], ssq[4];
    asm("mov.b64 {%0, %1}, %2;" : "=f"(sum[0]), "=f"(sum[1]) : "l"(sum01));
    asm("mov.b64 {%0, %1}, %2;" : "=f"(sum[2]), "=f"(sum[3]) : "l"(sum23));
    asm("mov.b64 {%0, %1}, %2;" : "=f"(ssq[0]), "=f"(ssq[1]) : "l"(ssq01));
    asm("mov.b64 {%0, %1}, %2;" : "=f"(ssq[2]), "=f"(ssq[3]) : "l"(ssq23));

    // ---- parity-preserving warp reduction (masks 2..16 keep even/odd separate) ----
#pragma unroll
    for (int m = 2; m < 32; m <<= 1) {
#pragma unroll
        for (int j = 0; j < 4; j++) {
            sum[j]  += __shfl_xor_sync(0xffffffffu, sum[j], m);
            ssq[j]  += __shfl_xor_sync(0xffffffffu, ssq[j], m);
            cpos[j] += __shfl_xor_sync(0xffffffffu, cpos[j], m);
            cbel[j] += __shfl_xor_sync(0xffffffffu, cbel[j], m);
        }
    }
    if (lane < 2) {
#pragma unroll
        for (int j = 0; j < 4; j++) {
            int c = lane * 4 + j;
            sm->wpart[wid][c][0] = sum[j];
            sm->wpart[wid][c][1] = ssq[j];
            sm->wpart[wid][c][2] = (float)cpos[j];
            sm->wbelow[wid][c]   = cbel[j];
        }
    }
    __syncthreads();

    // ---- deterministic block combine ----
    if (tid < C_DIM) {
        float S = 0.f, Q = 0.f, P = 0.f; int Bl = 0;
        for (int w = 0; w < NWARPS; w++) {
            S  += sm->wpart[w][tid][0];
            Q  += sm->wpart[w][tid][1];
            P  += sm->wpart[w][tid][2];
            Bl += sm->wbelow[w][tid];
        }
        float mean = S / (float)T_DIM;
        float var  = (Q - S * S / (float)T_DIM) / (float)(T_DIM - 1);
        sm->stat[tid][1] = mean;
        sm->stat[tid][2] = P;
        sm->stat[tid][3] = sqrtf(fmaxf(var, 0.0f));
        sm->below[tid]   = Bl;
    }
    __syncthreads();

    // ---- per-channel: compact private slots -> candidate list, then radix select ----
    if (wid < C_DIM) {
        const int c   = wid;
        const int j   = c & 3;
        const int par = c >> 2;
        int nc = 0;
        if (!sm->fb[c]) {
#pragma unroll 1
            for (int i = lane; i < (NT / 2) * SLOTS; i += 32) {
                int tt   = i & (NT / 2 - 1);
                int slot = i / (NT / 2);
                int tid2 = (tt << 1) | par;
                uint32_t cnt = (sm->cntp[tid2] >> (j * 8)) & 0xFFu;
                if (cnt > SLOTS) cnt = SLOTS;
                bool valid = (uint32_t)slot < cnt;
                float v = sm->priv[slot][j][tid2];
                uint32_t m = __ballot_sync(0xffffffffu, valid);
                int pos = nc + __popc(m & ((1u << lane) - 1u));
                if (valid && pos < CAP) sm->cand[c][pos] = v;
                nc += __popc(m);
            }
            int cb = sm->below[c];
            int l0 = RANK0 - cb;
            bool ok = (nc <= CAP) && (l0 >= 0) && (l0 + 1 < nc);
            if (ok) {
                float v0 = warp_select(sm->cand[c], sm->hist[c], nc, l0);
                float v1 = warp_select(sm->cand[c], sm->hist[c], nc, l0 + 1);
                if (lane == 0) sm->stat[c][0] = v0 + kFrac * (v1 - v0);
            } else {
                if (lane == 0) sm->fb[c] = 1;
            }
        }
    }
    __syncthreads();

    // ---- exact fallback (block-wide; statistically ~15 channels per whole run) ----
    for (int c = 0; c < C_DIM; c++) {
        if (sm->fb[c]) {
            float v0 = block_select_global(x, b, c, RANK0,     sm->bhist, sm->bcast);
            float v1 = block_select_global(x, b, c, RANK0 + 1, sm->bhist, sm->bcast);
            if (tid == 0) sm->stat[c][0] = v0 + kFrac * (v1 - v0);
            __syncthreads();
        }
    }

    // ---- tiny linear layer: feats order [q, mean, cnt, std] per channel ----
    if (tid < C_DIM) {
        float acc = sm->stat[tid][0] * __ldg(&W[tid * 4 + 0])
                  + sm->stat[tid][1] * __ldg(&W[tid * 4 + 1])
                  + sm->stat[tid][2] * __ldg(&W[tid * 4 + 2])
                  + sm->stat[tid][3] * __ldg(&W[tid * 4 + 3]);
        acc += __shfl_xor_sync(0xffu, acc, 1);
        acc += __shfl_xor_sync(0xffu, acc, 2);
        acc += __shfl_xor_sync(0xffu, acc, 4);
        if (tid == 0) out[b] = acc + __ldg(&bias[0]);
    }
}

extern "C" void kernel_launch(void* const* d_in, const int* in_sizes, int n_in,
                              void* d_out, int out_size) {
    const float* x    = (const float*)d_in[0];
    const float* W    = (const float*)d_in[1];
    const float* bias = (const float*)d_in[2];
    float* out        = (float*)d_out;
    int B = in_sizes[0] / (T_DIM * C_DIM);
    cudaFuncSetAttribute(stat_kernel, cudaFuncAttributeMaxDynamicSharedMemorySize,
                         (int)sizeof(SmemLayout));
    stat_kernel<<<B, NT, sizeof(SmemLayout)>>>(x, W, bias, out);
}